// round 5
// baseline (speedup 1.0000x reference)
#include <cuda_runtime.h>

#define S_ 4096
#define C_ 512
#define E_ 512

// Scratch (allocation-free rule: __device__ globals). 16 MB each.
__device__ float g_q[2ll * S_ * E_];
__device__ float g_k[2ll * S_ * E_];
__device__ float g_v[2ll * S_ * E_];
__device__ float g_o[2ll * S_ * E_];

__device__ __forceinline__ float ex2f_(float x) {
    float y;
    asm("ex2.approx.ftz.f32 %0, %1;" : "=f"(y) : "f"(x));
    return y;
}

// ---------------------------------------------------------------------------
// QKV projection: out[b][s][e] = sum_c A[b][c][s] * W[e][c] + bias[e]
// A is x (for q) or context (for k, v), layout [b][c][s] (s contiguous).
// grid = (E/64, S/64, 2*3); block = 256; 64x64 tile, K-chunk 32, 4x4 micro.
// ---------------------------------------------------------------------------
__global__ __launch_bounds__(256) void proj_kernel(
    const float* __restrict__ x, const float* __restrict__ ctx,
    const float* __restrict__ Wq, const float* __restrict__ bq,
    const float* __restrict__ Wk, const float* __restrict__ bk,
    const float* __restrict__ Wv, const float* __restrict__ bv)
{
    int et = blockIdx.x << 6;
    int st = blockIdx.y << 6;
    int z = blockIdx.z;
    int b = z / 3;
    int which = z - b * 3;
    const float* A = ((which == 0) ? x : ctx) + (size_t)b * C_ * S_;
    const float* W;
    const float* bias;
    float* out;
    if (which == 0)      { W = Wq; bias = bq; out = g_q; }
    else if (which == 1) { W = Wk; bias = bk; out = g_k; }
    else                 { W = Wv; bias = bv; out = g_v; }
    out += (size_t)b * S_ * E_;

    __shared__ __align__(16) float As[32][64];  // [c-chunk][s]
    __shared__ float Ws[64][33];                // [e][c-chunk], padded

    int t = threadIdx.x;
    int tx = t & 15, ty = t >> 4;
    float acc[4][4] = {};

    for (int c0 = 0; c0 < C_; c0 += 32) {
        #pragma unroll
        for (int r = 0; r < 2; r++) {
            int f = t + (r << 8);
            int row = f >> 4, col = (f & 15) << 2;
            float4 v = *reinterpret_cast<const float4*>(&A[(size_t)(c0 + row) * S_ + st + col]);
            *reinterpret_cast<float4*>(&As[row][col]) = v;
        }
        #pragma unroll
        for (int r = 0; r < 2; r++) {
            int f = t + (r << 8);
            int row = f >> 3, cq = (f & 7) << 2;
            float4 v = *reinterpret_cast<const float4*>(&W[(size_t)(et + row) * C_ + c0 + cq]);
            Ws[row][cq + 0] = v.x; Ws[row][cq + 1] = v.y;
            Ws[row][cq + 2] = v.z; Ws[row][cq + 3] = v.w;
        }
        __syncthreads();
        #pragma unroll
        for (int cc = 0; cc < 32; cc++) {
            float a[4], w[4];
            #pragma unroll
            for (int i = 0; i < 4; i++) a[i] = As[cc][4 * ty + i];
            #pragma unroll
            for (int j = 0; j < 4; j++) w[j] = Ws[4 * tx + j][cc];
            #pragma unroll
            for (int i = 0; i < 4; i++)
                #pragma unroll
                for (int j = 0; j < 4; j++)
                    acc[i][j] = fmaf(a[i], w[j], acc[i][j]);
        }
        __syncthreads();
    }

    float4 bb = *reinterpret_cast<const float4*>(&bias[et + 4 * tx]);
    #pragma unroll
    for (int i = 0; i < 4; i++) {
        float4 o;
        o.x = acc[i][0] + bb.x; o.y = acc[i][1] + bb.y;
        o.z = acc[i][2] + bb.z; o.w = acc[i][3] + bb.w;
        *reinterpret_cast<float4*>(&out[(size_t)(st + 4 * ty + i) * E_ + et + 4 * tx]) = o;
    }
}

// ---------------------------------------------------------------------------
// Flash attention, fp32. One block = (b, head, 64-row q tile).
// Online softmax in log2 domain. K tile XOR-swizzled (16B granules) so
// row-major LDS.128 reads are conflict-free; P overwrites the K buffer.
// ---------------------------------------------------------------------------
__global__ __launch_bounds__(256, 2) void attn_kernel()
{
    __shared__ __align__(16) float Qs[64 * 64];
    __shared__ __align__(16) float KP[64 * 64];  // K (swizzled) then P (plain)
    __shared__ __align__(16) float Vs[64 * 64];

    int st = blockIdx.x << 6;
    int h  = blockIdx.y;
    int b  = blockIdx.z;
    const float* qg = g_q + ((size_t)b * S_ + st) * E_ + h * 64;
    const float* kg = g_k + (size_t)b * S_ * E_ + h * 64;
    const float* vg = g_v + (size_t)b * S_ * E_ + h * 64;

    int t = threadIdx.x, tx = t & 15, ty = t >> 4;

    #pragma unroll
    for (int r = 0; r < 4; r++) {
        int f = t + (r << 8);
        int row = f >> 4, g = f & 15;
        *reinterpret_cast<float4*>(&Qs[row * 64 + 4 * g]) =
            *reinterpret_cast<const float4*>(&qg[(size_t)row * E_ + 4 * g]);
    }

    float m[4], l[4], acco[4][4] = {};
    #pragma unroll
    for (int i = 0; i < 4; i++) { m[i] = -1e30f; l[i] = 0.f; }

    const float SC = 0.125f * 1.4426950408889634f;  // scale * log2(e)

    for (int kt = 0; kt < S_; kt += 64) {
        __syncthreads();  // previous iteration done reading KP(P)/Vs; Q ready
        #pragma unroll
        for (int r = 0; r < 4; r++) {
            int f = t + (r << 8);
            int row = f >> 4, g = f & 15;
            float4 kv = *reinterpret_cast<const float4*>(&kg[(size_t)(kt + row) * E_ + 4 * g]);
            *reinterpret_cast<float4*>(&KP[row * 64 + 4 * (g ^ (row & 15))]) = kv;
            float4 vv = *reinterpret_cast<const float4*>(&vg[(size_t)(kt + row) * E_ + 4 * g]);
            *reinterpret_cast<float4*>(&Vs[row * 64 + 4 * g]) = vv;
        }
        __syncthreads();

        // S = Q K^T (4x4 micro, vectorized over d)
        float s[4][4] = {};
        #pragma unroll
        for (int d4 = 0; d4 < 16; d4++) {
            float4 q4[4];
            #pragma unroll
            for (int i = 0; i < 4; i++)
                q4[i] = *reinterpret_cast<const float4*>(&Qs[(4 * ty + i) * 64 + 4 * d4]);
            #pragma unroll
            for (int j = 0; j < 4; j++) {
                int R = 4 * tx + j;
                float4 k4 = *reinterpret_cast<const float4*>(
                    &KP[R * 64 + 4 * (d4 ^ (R & 15))]);
                #pragma unroll
                for (int i = 0; i < 4; i++) {
                    s[i][j] = fmaf(q4[i].x, k4.x, s[i][j]);
                    s[i][j] = fmaf(q4[i].y, k4.y, s[i][j]);
                    s[i][j] = fmaf(q4[i].z, k4.z, s[i][j]);
                    s[i][j] = fmaf(q4[i].w, k4.w, s[i][j]);
                }
            }
        }

        // Online softmax update (rows owned by 16-lane groups)
        #pragma unroll
        for (int i = 0; i < 4; i++) {
            float rm = -1e30f;
            #pragma unroll
            for (int j = 0; j < 4; j++) { s[i][j] *= SC; rm = fmaxf(rm, s[i][j]); }
            #pragma unroll
            for (int o = 8; o; o >>= 1) rm = fmaxf(rm, __shfl_xor_sync(0xffffffffu, rm, o));
            float mn = fmaxf(m[i], rm);
            float corr = ex2f_(m[i] - mn);
            float rs = 0.f;
            #pragma unroll
            for (int j = 0; j < 4; j++) { s[i][j] = ex2f_(s[i][j] - mn); rs += s[i][j]; }
            #pragma unroll
            for (int o = 8; o; o >>= 1) rs += __shfl_xor_sync(0xffffffffu, rs, o);
            l[i] = l[i] * corr + rs;
            #pragma unroll
            for (int j = 0; j < 4; j++) acco[i][j] *= corr;
            m[i] = mn;
        }

        __syncthreads();  // everyone done reading KP as K
        #pragma unroll
        for (int i = 0; i < 4; i++) {
            float4 p;
            p.x = s[i][0]; p.y = s[i][1]; p.z = s[i][2]; p.w = s[i][3];
            *reinterpret_cast<float4*>(&KP[(4 * ty + i) * 64 + 4 * tx]) = p;
        }
        __syncthreads();  // P visible

        // O += P V (vectorized over cols)
        #pragma unroll
        for (int c4 = 0; c4 < 16; c4++) {
            float4 p4[4];
            #pragma unroll
            for (int i = 0; i < 4; i++)
                p4[i] = *reinterpret_cast<const float4*>(&KP[(4 * ty + i) * 64 + 4 * c4]);
            #pragma unroll
            for (int cc = 0; cc < 4; cc++) {
                float4 v4 = *reinterpret_cast<const float4*>(&Vs[(4 * c4 + cc) * 64 + 4 * tx]);
                #pragma unroll
                for (int i = 0; i < 4; i++) {
                    float p = (cc == 0) ? p4[i].x : (cc == 1) ? p4[i].y
                            : (cc == 2) ? p4[i].z : p4[i].w;
                    acco[i][0] = fmaf(p, v4.x, acco[i][0]);
                    acco[i][1] = fmaf(p, v4.y, acco[i][1]);
                    acco[i][2] = fmaf(p, v4.z, acco[i][2]);
                    acco[i][3] = fmaf(p, v4.w, acco[i][3]);
                }
            }
        }
    }

    float* og = g_o + ((size_t)b * S_ + st) * E_ + h * 64;
    #pragma unroll
    for (int i = 0; i < 4; i++) {
        float inv = 1.f / l[i];
        float4 o;
        o.x = acco[i][0] * inv; o.y = acco[i][1] * inv;
        o.z = acco[i][2] * inv; o.w = acco[i][3] * inv;
        *reinterpret_cast<float4*>(&og[(size_t)(4 * ty + i) * E_ + 4 * tx]) = o;
    }
}

// ---------------------------------------------------------------------------
// Output projection: y[b][c][s] = sum_e O[b][s][e] * Wo[c][e] + bo[c]
// grid = (S/64, C/64, 2)
// ---------------------------------------------------------------------------
__global__ __launch_bounds__(256) void oproj_kernel(
    const float* __restrict__ Wo, const float* __restrict__ bo, float* __restrict__ y)
{
    int st = blockIdx.x << 6;
    int ct = blockIdx.y << 6;
    int b  = blockIdx.z;
    const float* O = g_o + (size_t)b * S_ * E_;

    __shared__ float Ws2[64][33];  // Wo [c][e-chunk]
    __shared__ float Os[64][33];   // O  [s][e-chunk]

    int t = threadIdx.x, tx = t & 15, ty = t >> 4;
    float acc[4][4] = {};

    for (int e0 = 0; e0 < E_; e0 += 32) {
        #pragma unroll
        for (int r = 0; r < 2; r++) {
            int f = t + (r << 8);
            int row = f >> 3, cq = (f & 7) << 2;
            float4 wv = *reinterpret_cast<const float4*>(&Wo[(size_t)(ct + row) * E_ + e0 + cq]);
            Ws2[row][cq + 0] = wv.x; Ws2[row][cq + 1] = wv.y;
            Ws2[row][cq + 2] = wv.z; Ws2[row][cq + 3] = wv.w;
            float4 ov = *reinterpret_cast<const float4*>(&O[(size_t)(st + row) * E_ + e0 + cq]);
            Os[row][cq + 0] = ov.x; Os[row][cq + 1] = ov.y;
            Os[row][cq + 2] = ov.z; Os[row][cq + 3] = ov.w;
        }
        __syncthreads();
        #pragma unroll
        for (int ee = 0; ee < 32; ee++) {
            float a[4], o4[4];
            #pragma unroll
            for (int i = 0; i < 4; i++) a[i] = Ws2[4 * ty + i][ee];
            #pragma unroll
            for (int j = 0; j < 4; j++) o4[j] = Os[4 * tx + j][ee];
            #pragma unroll
            for (int i = 0; i < 4; i++)
                #pragma unroll
                for (int j = 0; j < 4; j++)
                    acc[i][j] = fmaf(a[i], o4[j], acc[i][j]);
        }
        __syncthreads();
    }

    #pragma unroll
    for (int i = 0; i < 4; i++) {
        float bb = bo[ct + 4 * ty + i];
        float4 o;
        o.x = acc[i][0] + bb; o.y = acc[i][1] + bb;
        o.z = acc[i][2] + bb; o.w = acc[i][3] + bb;
        *reinterpret_cast<float4*>(&y[((size_t)b * C_ + ct + 4 * ty + i) * S_ + st + 4 * tx]) = o;
    }
}

extern "C" void kernel_launch(void* const* d_in, const int* in_sizes, int n_in,
                              void* d_out, int out_size)
{
    const float* x   = (const float*)d_in[0];
    const float* ctx = (const float*)d_in[1];
    const float* Wq  = (const float*)d_in[2];
    const float* bq  = (const float*)d_in[3];
    const float* Wk  = (const float*)d_in[4];
    const float* bk  = (const float*)d_in[5];
    const float* Wv  = (const float*)d_in[6];
    const float* bv  = (const float*)d_in[7];
    const float* Wo  = (const float*)d_in[8];
    const float* bo  = (const float*)d_in[9];
    float* y = (float*)d_out;

    proj_kernel<<<dim3(E_ / 64, S_ / 64, 6), 256>>>(x, ctx, Wq, bq, Wk, bk, Wv, bv);
    attn_kernel<<<dim3(S_ / 64, 8, 2), 256>>>();
    oproj_kernel<<<dim3(S_ / 64, C_ / 64, 2), 256>>>(Wo, bo, y);
}